// round 11
// baseline (speedup 1.0000x reference)
#include <cuda_runtime.h>
#include <cuda_fp16.h>
#include <stdint.h>

// Problem constants
#define BATCH 8
#define LQ    1024
#define LKV   2048
#define HID   1024
#define QDIM  1024

typedef __half f16;

// ================= scratch (static device globals) =================
__device__ __align__(16) f16 g_qc [(size_t)BATCH * LQ  * QDIM];   // query fp16
__device__ __align__(16) f16 g_kvcomp[(size_t)BATCH * LKV * QDIM]; // compacted kv fp16
__device__ __align__(16) f16 g_WqT[(size_t)HID * QDIM];
__device__ __align__(16) f16 g_WkT[(size_t)HID * QDIM];
__device__ __align__(16) f16 g_WvT[(size_t)HID * QDIM];
__device__ __align__(16) f16 g_WoT[(size_t)HID * QDIM];
__device__ __align__(16) f16  g_Qh [(size_t)BATCH * LQ  * HID];
__device__ __align__(16) f16  g_Kh [(size_t)BATCH * LKV * HID];   // compacted K
__device__ __align__(16) f16  g_VT [(size_t)BATCH * HID * LKV];   // compacted V^T
__device__ __align__(16) float g_Sf [(size_t)BATCH * LQ  * LKV];  // compacted scores
__device__ __align__(16) f16  g_Ph [(size_t)BATCH * LQ  * LKV];   // compacted probs
__device__ __align__(16) f16  g_Ch [(size_t)BATCH * LQ  * HID];
__device__ int g_idx[(size_t)BATCH * LKV];   // compaction index
__device__ int g_nvalid[BATCH];
__device__ int g_lkvp[BATCH];                // nvalid rounded up to 128
__device__ int g_mask_is_u8;

// ================= PTX helpers =================
__device__ __forceinline__ uint32_t smem_to_u32(const void* p) {
    uint32_t a;
    asm("{ .reg .u64 t; cvta.to.shared.u64 t, %1; cvt.u32.u64 %0, t; }"
        : "=r"(a) : "l"(p));
    return a;
}

#define SWZ128(o) ((o) ^ (((o) >> 3) & 0x70))

__device__ __forceinline__ void cp16(uint32_t saddr, const void* g) {
    asm volatile("cp.async.cg.shared.global [%0], [%1], 16;"
                 :: "r"(saddr), "l"(g) : "memory");
}
#define CP_COMMIT() asm volatile("cp.async.commit_group;" ::: "memory")
#define CP_WAIT1()  asm volatile("cp.async.wait_group 1;" ::: "memory")
#define CP_WAIT0()  asm volatile("cp.async.wait_group 0;" ::: "memory")

__device__ __forceinline__ void ldsm4(uint32_t* r, uint32_t addr) {
    asm volatile("ldmatrix.sync.aligned.m8n8.x4.shared.b16 {%0,%1,%2,%3}, [%4];"
                 : "=r"(r[0]), "=r"(r[1]), "=r"(r[2]), "=r"(r[3]) : "r"(addr));
}

__device__ __forceinline__ void mma16816(float* d, const uint32_t* a,
                                         uint32_t b0, uint32_t b1) {
    asm volatile(
        "mma.sync.aligned.m16n8k16.row.col.f32.f16.f16.f32 "
        "{%0,%1,%2,%3}, {%4,%5,%6,%7}, {%8,%9}, {%0,%1,%2,%3};"
        : "+f"(d[0]), "+f"(d[1]), "+f"(d[2]), "+f"(d[3])
        : "r"(a[0]), "r"(a[1]), "r"(a[2]), "r"(a[3]), "r"(b0), "r"(b1));
}

// ================= mask detect + compaction =================
__global__ void detect_mask_kernel(const void* __restrict__ mask_raw) {
    __shared__ int bad;
    if (threadIdx.x == 0) bad = 0;
    __syncthreads();
    const int* w = (const int*)mask_raw;
    for (int i = threadIdx.x; i < 4096; i += blockDim.x)
        if ((unsigned)w[i] > 1u) atomicOr(&bad, 1);
    __syncthreads();
    if (threadIdx.x == 0) g_mask_is_u8 = bad;
}

// One block per batch: block-scan over 2048 mask values -> g_idx/g_nvalid/g_lkvp.
__global__ void __launch_bounds__(256)
build_compact_kernel(const void* __restrict__ mask_raw)
{
    const int b   = blockIdx.x;
    const int tid = threadIdx.x;
    const int is_u8 = g_mask_is_u8;
    const int base = tid * 8;

    int m[8], cnt = 0;
    #pragma unroll
    for (int i = 0; i < 8; i++) {
        const int gi = b * LKV + base + i;
        int v = is_u8 ? (((const uint8_t*)mask_raw)[gi] != 0)
                      : (((const int*)mask_raw)[gi] != 0);
        m[i] = v;
        cnt += v;
    }

    const int lane = tid & 31, w = tid >> 5;
    int v = cnt;
    #pragma unroll
    for (int o = 1; o < 32; o <<= 1) {
        int t = __shfl_up_sync(0xFFFFFFFFu, v, o);
        if (lane >= o) v += t;
    }
    __shared__ int ws[8];
    if (lane == 31) ws[w] = v;
    __syncthreads();
    __shared__ int total;
    if (tid == 0) {
        int s = 0;
        #pragma unroll
        for (int i = 0; i < 8; i++) { int t = ws[i]; ws[i] = s; s += t; }
        total = s;
    }
    __syncthreads();
    int pos = v - cnt + ws[w];

    #pragma unroll
    for (int i = 0; i < 8; i++)
        if (m[i]) g_idx[b * LKV + pos++] = base + i;

    if (tid == 0) {
        g_nvalid[b] = total;
        g_lkvp[b]   = (total + 127) & ~127;
    }
}

// Gather + fp32->fp16 convert: kvcomp[b][j] = kv[b][idx[b][j]] ; pad rows = 0.
__global__ void __launch_bounds__(128)
gather_kv_kernel(const float* __restrict__ kv)
{
    const int j = blockIdx.x, b = blockIdx.y, t = threadIdx.x;
    if (j >= g_lkvp[b]) return;
    f16* dst = g_kvcomp + ((size_t)b * LKV + j) * QDIM;
    if (j < g_nvalid[b]) {
        const float* src = kv + ((size_t)b * LKV + g_idx[b * LKV + j]) * QDIM;
        float4 a = *(const float4*)(src + t * 8);
        float4 c = *(const float4*)(src + t * 8 + 4);
        f16 h[8] = {__float2half_rn(a.x), __float2half_rn(a.y),
                    __float2half_rn(a.z), __float2half_rn(a.w),
                    __float2half_rn(c.x), __float2half_rn(c.y),
                    __float2half_rn(c.z), __float2half_rn(c.w)};
        *(uint4*)(dst + t * 8) = *(uint4*)h;
    } else {
        *(uint4*)(dst + t * 8) = make_uint4(0, 0, 0, 0);
    }
}

// ================= elementwise fp32 -> fp16 convert =================
__global__ void __launch_bounds__(256)
convert_kernel(const float* __restrict__ x, f16* __restrict__ h, long long n4)
{
    long long i = blockIdx.x * 256 + threadIdx.x;
    if (i >= n4) return;
    float4 v = *(const float4*)(x + i * 4);
    f16 hh[4] = {__float2half_rn(v.x), __float2half_rn(v.y),
                 __float2half_rn(v.z), __float2half_rn(v.w)};
    *(uint2*)(h + i * 4) = *(uint2*)hh;
}

// ======= batched 1024x1024 transpose: W[z][R][C] fp32 -> WT[z][C][R] fp16 =======
struct WTArgs {
    const float* src[4];
    f16*         dst[4];
};

__global__ void __launch_bounds__(256)
wtrans_kernel(WTArgs args)
{
    __shared__ float t[32][33];
    const float* x = args.src[blockIdx.z];
    f16*        th = args.dst[blockIdx.z];
    const int bc = blockIdx.x * 32;
    const int br = blockIdx.y * 32;
    const int tx = threadIdx.x, ty = threadIdx.y;
    #pragma unroll
    for (int j = 0; j < 32; j += 8)
        t[ty + j][tx] = x[(long long)(br + ty + j) * 1024 + bc + tx];
    __syncthreads();
    #pragma unroll
    for (int j = 0; j < 32; j += 8)
        th[(long long)(bc + ty + j) * 1024 + br + tx] = __float2half_rn(t[tx][ty + j]);
}

// ================= persistent single-pass fp16 HMMA GEMM =================
// C[M,N] = A[M,K] @ B[N,K]^T, fp32 accumulate.
// CTA 128x128 tile, K-tile 64, 8 warps (4M x 2N), 3-stage cp.async pipeline.
// Persistent: 1-D grid strides over linearized (gz, gy, gx) tile space.
// EPI: 0=+bias[col]->f16 ; 1=+bias[col]->fp32 ; 2=compact mask*scale->fp32 ;
//      3=plain->f16 ; 5=+bias[row]->f16 (transposed projection)
// VAR: 0=none ; 1=M limited by lkvp[b] ; 2=N limited (EPI2 masks by nvalid) ;
//      3=K runtime = lkvp[b]
#define BKT 64
#define STAGE_B 32768
#define NSTAGE 3
#define DSMEM_B (NSTAGE * STAGE_B)   // 96KB

template <int EPI, int VAR>
__global__ void __launch_bounds__(256, 2)
mma_gemm(const f16* __restrict__ A, const f16* __restrict__ B,
         float* __restrict__ Cf, f16* __restrict__ Oh,
         const float* __restrict__ bias,
         const int* __restrict__ d_nv, const int* __restrict__ d_lkvp,
         float scale, int N, int KdHost, int ldA, int ldB,
         long long sA, long long sB, long long sC,
         int gx, int gy, int gz)
{
    extern __shared__ char smem[];
    const uint32_t sbase = smem_to_u32(smem);

    const int tid  = threadIdx.x;
    const int wid = tid >> 5, lane = tid & 31;
    const int wm = wid & 3;
    const int wn = wid >> 2;
    const int ntiles = gx * gy * gz;

    for (int t = blockIdx.x; t < ntiles; t += gridDim.x) {
        const int b  = t / (gx * gy);
        const int r2 = t - b * (gx * gy);
        const int ty = r2 / gx;
        const int tx = r2 - ty * gx;
        const int tileM = ty * 128;
        const int tileN = tx * 128;

        int lim = 0;
        if (VAR != 0) lim = d_lkvp[b];
        if (VAR == 1 && tileM >= lim) continue;
        if (VAR == 2 && tileN >= lim) continue;
        const int Kd = (VAR == 3) ? lim : KdHost;

        const f16* baseA = A + (long long)b * sA + (long long)tileM * ldA;
        const f16* baseB = B + (long long)b * sB + (long long)tileN * ldB;

        float acc[2][8][4];
        #pragma unroll
        for (int mi = 0; mi < 2; mi++)
            #pragma unroll
            for (int nj = 0; nj < 8; nj++)
                #pragma unroll
                for (int q = 0; q < 4; q++) acc[mi][nj][q] = 0.0f;

        const int KT = Kd / BKT;

        auto load_stage = [&](int kt, int s) {
            const int k0 = kt * BKT;
            #pragma unroll
            for (int sub = 0; sub < 2; sub++) {
                const f16* gb = sub ? baseB : baseA;
                const int ld  = sub ? ldB : ldA;
                const uint32_t so = sbase + s * STAGE_B + sub * 16384;
                #pragma unroll
                for (int i = 0; i < 4; i++) {
                    const int c  = i * 256 + tid;
                    const int r  = c >> 3;
                    const int kc = c & 7;
                    cp16(so + SWZ128((uint32_t)(r * 128 + kc * 16)),
                         gb + (long long)r * ld + k0 + kc * 8);
                }
            }
            CP_COMMIT();
        };

        load_stage(0, 0);
        if (KT > 1) load_stage(1, 1);

        for (int kt = 0; kt < KT; kt++) {
            const int s = kt % NSTAGE;
            if (kt + 1 < KT) CP_WAIT1(); else CP_WAIT0();
            __syncthreads();
            if (kt + 2 < KT) load_stage(kt + 2, (kt + 2) % NSTAGE);

            const uint32_t aS = sbase + s * STAGE_B;
            const uint32_t bS = aS + 16384;

            #pragma unroll
            for (int ks = 0; ks < 4; ks++) {
                const int chunk = ks * 32 + (lane >> 4) * 16;
                uint32_t af[2][4];
                #pragma unroll
                for (int mi = 0; mi < 2; mi++) {
                    const int r = wm * 32 + mi * 16 + (lane & 15);
                    ldsm4(af[mi], aS + SWZ128((uint32_t)(r * 128 + chunk)));
                }
                uint32_t bf[4][4];
                #pragma unroll
                for (int ni = 0; ni < 4; ni++) {
                    const int r = wn * 64 + ni * 16 + (lane & 15);
                    ldsm4(bf[ni], bS + SWZ128((uint32_t)(r * 128 + chunk)));
                }
                #pragma unroll
                for (int mi = 0; mi < 2; mi++) {
                    #pragma unroll
                    for (int nj = 0; nj < 8; nj++) {
                        const int ni = nj >> 1, oct = nj & 1;
                        mma16816(acc[mi][nj], af[mi], bf[ni][oct], bf[ni][oct + 2]);
                    }
                }
            }
        }

        // ---- epilogue ----
        float* cf = Cf ? Cf + (long long)b * sC : nullptr;
        f16*   oh = Oh ? Oh + (long long)b * sC : nullptr;
        const int nv = (VAR == 2 && EPI == 2) ? d_nv[b] : 0;

        #pragma unroll
        for (int mi = 0; mi < 2; mi++) {
            #pragma unroll
            for (int nj = 0; nj < 8; nj++) {
                const int row = tileM + wm * 32 + mi * 16 + (lane >> 2);
                const int col = tileN + wn * 64 + nj * 8 + (lane & 3) * 2;
                #pragma unroll
                for (int half = 0; half < 2; half++) {
                    const int r = row + half * 8;
                    float v0 = acc[mi][nj][half * 2];
                    float v1 = acc[mi][nj][half * 2 + 1];
                    if (EPI == 0 || EPI == 1) {
                        v0 += __ldg(bias + col);
                        v1 += __ldg(bias + col + 1);
                    } else if (EPI == 2) {
                        v0 = (col     < nv) ? v0 * scale : -1e9f;
                        v1 = (col + 1 < nv) ? v1 * scale : -1e9f;
                    } else if (EPI == 5) {
                        const float bv = __ldg(bias + r);
                        v0 += bv;
                        v1 += bv;
                    }
                    if (EPI == 1 || EPI == 2) {
                        *(float2*)(cf + (long long)r * N + col) = make_float2(v0, v1);
                    } else {
                        f16 h2[2] = {__float2half_rn(v0), __float2half_rn(v1)};
                        *(uint32_t*)(oh + (long long)r * N + col) = *(uint32_t*)h2;
                    }
                }
            }
        }
        __syncthreads();   // all warps done with epilogue before next tile reuses smem
    }
}

// ============ softmax over compacted row length lkvp[b] ============
__global__ void __launch_bounds__(256)
softmax_kernel(const float* __restrict__ S, f16* __restrict__ Ph,
               const int* __restrict__ d_lkvp)
{
    const int b = blockIdx.x >> 10;          // LQ = 1024 rows per batch
    const int len = d_lkvp[b];
    const long long ro = (long long)blockIdx.x * LKV;
    const int tid = threadIdx.x;
    const bool active = (tid * 8) < len;

    float vals[8];
    if (active) {
        const float* row = S + ro + tid * 8;
        *(float4*)(vals)     = *(const float4*)(row);
        *(float4*)(vals + 4) = *(const float4*)(row + 4);
    } else {
        #pragma unroll
        for (int i = 0; i < 8; i++) vals[i] = -1e30f;
    }

    float mx = vals[0];
    #pragma unroll
    for (int i = 1; i < 8; i++) mx = fmaxf(mx, vals[i]);

    __shared__ float red[8];
    #pragma unroll
    for (int o = 16; o > 0; o >>= 1)
        mx = fmaxf(mx, __shfl_xor_sync(0xFFFFFFFFu, mx, o));
    if ((tid & 31) == 0) red[tid >> 5] = mx;
    __syncthreads();
    if (tid == 0) {
        float v = red[0];
        #pragma unroll
        for (int w = 1; w < 8; w++) v = fmaxf(v, red[w]);
        red[0] = v;
    }
    __syncthreads();
    mx = red[0];

    float sum = 0.0f;
    #pragma unroll
    for (int i = 0; i < 8; i++) {
        vals[i] = __expf(vals[i] - mx);
        sum += vals[i];
    }
    __syncthreads();
    #pragma unroll
    for (int o = 16; o > 0; o >>= 1)
        sum += __shfl_xor_sync(0xFFFFFFFFu, sum, o);
    if ((tid & 31) == 0) red[tid >> 5] = sum;
    __syncthreads();
    if (tid == 0) {
        float v = red[0];
        #pragma unroll
        for (int w = 1; w < 8; w++) v += red[w];
        red[0] = v;
    }
    __syncthreads();
    const float inv = 1.0f / red[0];

    if (active) {
        f16 h[8];
        #pragma unroll
        for (int i = 0; i < 8; i++) h[i] = __float2half_rn(vals[i] * inv);
        *(uint4*)(Ph + ro + tid * 8) = *(uint4*)h;
    }
}

// ================= host launcher =================
extern "C" void kernel_launch(void* const* d_in, const int* in_sizes, int n_in,
                              void* d_out, int out_size)
{
    const float* query = (const float*)d_in[0];
    const float* kv    = (const float*)d_in[1];
    const void*  mask  = d_in[2];
    const float* Wq = (const float*)d_in[3];
    const float* bq = (const float*)d_in[4];
    const float* Wk = (const float*)d_in[5];
    const float* bk = (const float*)d_in[6];
    const float* Wv = (const float*)d_in[7];
    const float* bv = (const float*)d_in[8];
    const float* Wo = (const float*)d_in[9];
    const float* bo = (const float*)d_in[10];
    float* out = (float*)d_out;

    f16 *qc, *kvcomp, *WqT, *WkT, *WvT, *WoT;
    f16 *Qh, *Kh, *VT, *Ph, *Ch;
    float *Sf;
    int *NV, *LK;
    cudaGetSymbolAddress((void**)&qc,  g_qc);
    cudaGetSymbolAddress((void**)&kvcomp, g_kvcomp);
    cudaGetSymbolAddress((void**)&WqT, g_WqT);  cudaGetSymbolAddress((void**)&WkT, g_WkT);
    cudaGetSymbolAddress((void**)&WvT, g_WvT);  cudaGetSymbolAddress((void**)&WoT, g_WoT);
    cudaGetSymbolAddress((void**)&Qh, g_Qh);    cudaGetSymbolAddress((void**)&Kh, g_Kh);
    cudaGetSymbolAddress((void**)&VT, g_VT);
    cudaGetSymbolAddress((void**)&Sf, g_Sf);    cudaGetSymbolAddress((void**)&Ph, g_Ph);
    cudaGetSymbolAddress((void**)&Ch, g_Ch);
    cudaGetSymbolAddress((void**)&NV, g_nvalid);
    cudaGetSymbolAddress((void**)&LK, g_lkvp);

    cudaFuncSetAttribute(mma_gemm<0,0>, cudaFuncAttributeMaxDynamicSharedMemorySize, DSMEM_B);
    cudaFuncSetAttribute(mma_gemm<0,1>, cudaFuncAttributeMaxDynamicSharedMemorySize, DSMEM_B);
    cudaFuncSetAttribute(mma_gemm<1,0>, cudaFuncAttributeMaxDynamicSharedMemorySize, DSMEM_B);
    cudaFuncSetAttribute(mma_gemm<2,2>, cudaFuncAttributeMaxDynamicSharedMemorySize, DSMEM_B);
    cudaFuncSetAttribute(mma_gemm<3,3>, cudaFuncAttributeMaxDynamicSharedMemorySize, DSMEM_B);
    cudaFuncSetAttribute(mma_gemm<5,2>, cudaFuncAttributeMaxDynamicSharedMemorySize, DSMEM_B);

    int nsm = 148;
    cudaDeviceGetAttribute(&nsm, cudaDevAttrMultiProcessorCount, 0);
    const int PGRID = nsm * 2;   // one balanced persistent wave (2 CTAs/SM)

    const float scale = 1.0f / 32.0f;  // 1/sqrt(1024)

    // 1. query convert
    convert_kernel<<<(int)(((long long)BATCH * LQ * QDIM / 4 + 255) / 256), 256>>>(
        query, qc, (long long)BATCH * LQ * QDIM / 4);

    // 2. all four weight transposes in one launch
    {
        WTArgs wa;
        wa.src[0] = Wq;  wa.dst[0] = WqT;
        wa.src[1] = Wk;  wa.dst[1] = WkT;
        wa.src[2] = Wv;  wa.dst[2] = WvT;
        wa.src[3] = Wo;  wa.dst[3] = WoT;
        wtrans_kernel<<<dim3(32, 32, 4), dim3(32, 8)>>>(wa);
    }

    // 3. mask detect
    detect_mask_kernel<<<1, 256>>>(mask);

    // 4. Q projection -> Qh   (ncu control; tiles 8 x 64 x 1)
    mma_gemm<0,0><<<PGRID, 256, DSMEM_B>>>(
        qc, WqT, nullptr, Qh, bq, nullptr, nullptr, 0.0f,
        HID, QDIM, QDIM, QDIM, 0, 0, 0,
        HID / 128, (BATCH * LQ) / 128, 1);

    // 5-6. compaction + gather
    build_compact_kernel<<<BATCH, 256>>>(mask);
    gather_kv_kernel<<<dim3(LKV, BATCH), 128>>>(kv);

    // 7. K projection on compacted rows -> Kh (M limited by lkvp)
    mma_gemm<0,1><<<PGRID, 256, DSMEM_B>>>(
        kvcomp, WkT, nullptr, Kh, bk, NV, LK, 0.0f,
        HID, QDIM, QDIM, QDIM,
        (long long)LKV * QDIM, 0, (long long)LKV * HID,
        HID / 128, LKV / 128, BATCH);

    // 8. V projection DIRECTLY TRANSPOSED:
    //    VT[b][h][j] = sum_k WvT[h][k] * kvcomp[b][j][k] + bv[h]
    //    A = WvT (M=HID, no batch), B = kvcomp (N limited by lkvp), row-bias.
    //    Pad columns get bias-only values; harmless (P==0 there).
    mma_gemm<5,2><<<PGRID, 256, DSMEM_B>>>(
        WvT, kvcomp, nullptr, VT, bv, NV, LK, 0.0f,
        LKV, QDIM, QDIM, QDIM,
        0, (long long)LKV * QDIM, (long long)HID * LKV,
        LKV / 128, HID / 128, BATCH);

    // 9. scores (compact N): S = Q @ K^T, epilogue scale/-1e9 by nvalid
    mma_gemm<2,2><<<PGRID, 256, DSMEM_B>>>(
        Qh, Kh, Sf, nullptr, nullptr, NV, LK, scale,
        LKV, HID, HID, HID,
        (long long)LQ * HID, (long long)LKV * HID, (long long)LQ * LKV,
        LKV / 128, LQ / 128, BATCH);

    // 10. softmax over lkvp[b] -> Ph
    softmax_kernel<<<BATCH * LQ, 256>>>(Sf, Ph, LK);

    // 11. context (runtime K = lkvp[b]): C = P @ VT^T
    mma_gemm<3,3><<<PGRID, 256, DSMEM_B>>>(
        Ph, VT, nullptr, Ch, nullptr, NV, LK, 0.0f,
        HID, 0, LKV, LKV,
        (long long)LQ * LKV, (long long)HID * LKV, (long long)LQ * HID,
        HID / 128, LQ / 128, BATCH);

    // 12. output projection: out = C @ WoT^T + bo (fp32)
    mma_gemm<1,0><<<PGRID, 256, DSMEM_B>>>(
        Ch, WoT, out, nullptr, bo, nullptr, nullptr, 0.0f,
        QDIM, HID, HID, HID, 0, 0, 0,
        QDIM / 128, (BATCH * LQ) / 128, 1);
}